// round 16
// baseline (speedup 1.0000x reference)
#include <cuda_runtime.h>
#include <math.h>

#define NB 512
#define FDIM 4096
#define DEG 3
#define NTHREADS 512
#define BATCH 8192
#define NGROUPS (BATCH / 4)      // 2048 groups of 4 rows
#define GRID_MAIN 296            // 148 SMs x 2 CTAs
#define SCHEDROWS 96             // q2 (u32) rows per degree in the schedule

// Bank-scheduled gather tables (built once per launch, deterministic).
// sched entry (u16): PRE-SWIZZLED feature (13 bits; swizzle f^((f>>4)&3);
// 4096+b = zero-pad slot hitting bank b) | sign<<15 (1 -> +x).
__device__ __align__(16) unsigned g_sched[DEG * SCHEDROWS * 32];
__device__ __align__(16) unsigned short g_assign[DEG * NB];  // thread -> bucket
__device__ unsigned short g_glen2[DEG * 16];   // q2-rows per (deg, warp)
__device__ unsigned short g_gbase2[DEG * 16];  // q2-row base per (deg, warp)
__device__ unsigned g_ctr;

// intermediate CSR handed from build_csr to build_sched
__device__ __align__(16) unsigned short g_lists[DEG * FDIM];
__device__ __align__(16) unsigned short g_sortg[DEG * NB];
__device__ __align__(16) unsigned short g_cntg[DEG * NB];
__device__ __align__(16) int g_offg[DEG * (NB + 1)];
__device__ int g_rowsg[DEG * 16];
__device__ int g_base2g[DEG * 16];

// ---------------------------------------------------------------------------
// Prologue kernel 1: one block per degree.
// 1) invert hash into per-bucket lists (deterministic chunk-major order)
// 2) BANK-GROUP each bucket (stable counting sort, predicated unroll)
// 3) sort buckets by (len desc, id asc); warp w owns ranks [32w, 32w+32)
// 4) dump CSR + metadata to global for build_sched.
// ---------------------------------------------------------------------------
__global__ void __launch_bounds__(NTHREADS)
build_csr(const int* __restrict__ idxh, const int* __restrict__ bith)
{
    __shared__ int hist[8][NB];               // 16 KB
    __shared__ int scanA[NB], scanB[NB];      // 4 KB
    __shared__ int off[NB + 1];               // 2 KB
    __shared__ unsigned short lists[FDIM];    // 8 KB
    __shared__ unsigned short tmp[FDIM];      // 8 KB
    __shared__ unsigned short cnt[NB];        // 1 KB
    __shared__ unsigned short sortedIds[NB];  // 1 KB
    __shared__ int rowsArr[16], base2Arr[16];

    const int t = threadIdx.x;
    const int d = blockIdx.x;
    const int w = t >> 5, lane = t & 31;

    if (d == 0 && t == 0) g_ctr = 0;

    for (int i = t; i < 8 * NB; i += NTHREADS) ((int*)hist)[i] = 0;
    __syncthreads();

    if (w < 8) {   // chunk w = features [512w, 512w+512)
        const int base = d * FDIM + w * 512;
        for (int it = 0; it < 16; it++) {
            int b = idxh[base + it * 32 + lane];
            atomicAdd(&hist[w][b], 1);
        }
    }
    __syncthreads();

    {   // totals + inclusive scan -> off
        int c = 0;
        #pragma unroll
        for (int ch = 0; ch < 8; ch++) c += hist[ch][t];
        cnt[t] = (unsigned short)c;
        scanA[t] = c;
    }
    __syncthreads();
    {
        int* s = scanA; int* dd = scanB;
        for (int o = 1; o < NB; o <<= 1) {
            int v = s[t];
            if (t >= o) v += s[t - o];
            dd[t] = v;
            int* tmpp = s; s = dd; dd = tmpp;
            __syncthreads();
        }
        if (t == 0) off[0] = 0;
        off[t + 1] = s[t];
    }
    __syncthreads();
    {   // per-chunk cursors
        int base = off[t];
        #pragma unroll
        for (int c = 0; c < 8; c++) {
            int h = hist[c][t];
            hist[c][t] = base;
            base += h;
        }
    }
    __syncthreads();

    if (w < 8) {   // stable scatter into lists (pre-swizzled feature index)
        const int fbase = w * 512;
        for (int it = 0; it < 16; it++) {
            int f  = fbase + it * 32 + lane;
            int b  = idxh[d * FDIM + f];
            int sg = bith[d * FDIM + f];
            int fs = f ^ ((f >> 4) & 3);
            unsigned m = __match_any_sync(0xffffffffu, b);
            int rank = __popc(m & ((1u << lane) - 1));
            int grp  = __popc(m);
            int base = hist[w][b];
            lists[base + rank] = (unsigned short)(fs | (sg << 15));
            if (rank == grp - 1) hist[w][b] = base + grp;
            __syncwarp();
        }
    }
    __syncthreads();

    {   // BANK-GROUP bucket t: stable counting sort (static-unroll counters)
        const int o = off[t];
        const int n = cnt[t];
        int pos[16];
        #pragma unroll
        for (int b = 0; b < 16; b++) pos[b] = 0;
        for (int i = 0; i < n; i++) {
            const int bk = lists[o + i] & 15;
            #pragma unroll
            for (int b = 0; b < 16; b++) pos[b] += (bk == b);
        }
        int run = 0;
        #pragma unroll
        for (int b = 0; b < 16; b++) { int c = pos[b]; pos[b] = run; run += c; }
        for (int i = 0; i < n; i++) {
            const unsigned short e = lists[o + i];
            const int bk = e & 15;
            int dst = 0;
            #pragma unroll
            for (int b = 0; b < 16; b++) {
                if (bk == b) { dst = pos[b]; pos[b] = dst + 1; }
            }
            tmp[o + dst] = e;
        }
        for (int i = 0; i < n; i++) lists[o + i] = tmp[o + i];
    }
    __syncthreads();

    {   // deterministic sort by (len desc, id asc)
        const int myc = cnt[t];
        int gt = 0, eq = 0;
        for (int b2 = 0; b2 < NB; b2++) {
            int c2 = cnt[b2];
            gt += (c2 > myc);
            eq += (c2 == myc && b2 < t);
        }
        sortedIds[gt + eq] = (unsigned short)t;
    }
    __syncthreads();

    g_assign[d * NB + t] = sortedIds[t];

    // rows per warp = len of its longest bucket (lane 0 after sort), even-pad
    if (lane == 0) rowsArr[w] = ((int)cnt[sortedIds[32 * w]] + 1) & ~1;
    __syncthreads();
    if (t == 0) {
        int run = 0;
        for (int g = 0; g < 16; g++) { base2Arr[g] = run; run += rowsArr[g] >> 1; }
    }
    __syncthreads();
    if (lane == 0) {
        int gl = rowsArr[w] >> 1;
        const int b2 = base2Arr[w];
        if (b2 + gl > SCHEDROWS) gl = SCHEDROWS - b2;
        if (gl < 0) gl = 0;
        g_glen2[d * 16 + w]  = (unsigned short)gl;
        g_gbase2[d * 16 + w] = (unsigned short)b2;
    }

    // dump CSR for build_sched
    for (int i = t; i < FDIM; i += NTHREADS) g_lists[d * FDIM + i] = lists[i];
    g_sortg[d * NB + t] = sortedIds[t];
    g_cntg[d * NB + t]  = cnt[t];
    g_offg[d * (NB + 1) + t] = off[t];
    if (t == 0) g_offg[d * (NB + 1) + NB] = off[NB];
    if (t < 16) { g_rowsg[d * 16 + t] = rowsArr[t]; g_base2g[d * 16 + t] = base2Arr[t]; }
}

// ---------------------------------------------------------------------------
// Prologue kernel 2: greedy edge-coloring with REGISTER masks.
// grid=DEG, block=32: thread tid = problem (warp w2=tid>>1, half h=tid&1).
// Entries are bank-grouped, so `#pragma unroll b` + inner while gives
// static register indexing for f0/f1 — zero LDS/local on the serial chain.
// ---------------------------------------------------------------------------
__global__ void __launch_bounds__(32)
build_sched()
{
    __shared__ unsigned short sLists[FDIM];       // 8 KB
    __shared__ unsigned short sSort[NB];          // 1 KB
    __shared__ unsigned short sCnt[NB];           // 1 KB
    __shared__ int sOff[NB];                      // 2 KB

    const int d = blockIdx.x;
    const int tid = threadIdx.x;

    {   // cooperative stage of CSR into shared (vectorized)
        const uint4* src = (const uint4*)(g_lists + d * FDIM);
        uint4* dst = (uint4*)sLists;
        for (int i = tid; i < FDIM / 8; i += 32) dst[i] = src[i];
        const unsigned* s2 = (const unsigned*)(g_sortg + d * NB);
        unsigned* d2 = (unsigned*)sSort;
        for (int i = tid; i < NB / 2; i += 32) d2[i] = s2[i];
        const unsigned* s3 = (const unsigned*)(g_cntg + d * NB);
        unsigned* d3 = (unsigned*)sCnt;
        for (int i = tid; i < NB / 2; i += 32) d3[i] = s3[i];
        for (int i = tid; i < NB; i += 32) sOff[i] = g_offg[d * (NB + 1) + i];
    }
    __syncthreads();

    const int w2 = tid >> 1, h = tid & 1;
    const int rows   = g_rowsg[d * 16 + w2];
    const int base2v = g_base2g[d * 16 + w2];
    const unsigned long long full =
        (rows >= 64) ? ~0ull : ((1ull << rows) - 1ull);

    unsigned long long f0[16], f1[16];
    #pragma unroll
    for (int b = 0; b < 16; b++) { f0[b] = full; f1[b] = 0ull; }

    unsigned short* sched16 = (unsigned short*)g_sched;

    for (int l = 0; l < 16; l++) {
        const int L  = h * 16 + l;
        const int Bk = sSort[32 * w2 + L];
        const int o  = sOff[Bk];
        const int n  = sCnt[Bk];
        unsigned long long laneFree = full;
        int i = 0;
        #pragma unroll
        for (int b = 0; b < 16; b++) {
            while (i < n) {
                const unsigned short e = sLists[o + i];
                if ((int)(e & 15) != b) break;
                const unsigned long long c0 = f0[b] & laneFree;
                const unsigned long long c1 = f1[b] & laneFree;
                const unsigned long long pick = c0 ? c0 : (c1 ? c1 : laneFree);
                const int r = __ffsll((long long)pick) - 1;
                const unsigned long long bit = 1ull << r;
                if (f0[b] & bit)      { f0[b] &= ~bit; f1[b] |= bit; }
                else if (f1[b] & bit) { f1[b] &= ~bit; }
                laneFree &= ~bit;
                const int row2 = base2v + (r >> 1);
                if (row2 < SCHEDROWS)
                    sched16[((d * SCHEDROWS + row2) << 6) + L * 2 + (r & 1)] = e;
                i++;
            }
        }
        // pads: static-unroll scan for a row-free bank (updates masks)
        while (laneFree) {
            const int r = __ffsll((long long)laneFree) - 1;
            const unsigned long long bit = 1ull << r;
            laneFree &= ~bit;
            int ent = 0x1000 + (L & 15);
            bool found = false;
            #pragma unroll
            for (int b = 0; b < 16; b++) {
                if (!found && (f0[b] & bit)) {
                    f0[b] &= ~bit; f1[b] |= bit;
                    ent = 0x1000 + b; found = true;
                }
            }
            const int row2 = base2v + (r >> 1);
            if (row2 < SCHEDROWS)
                sched16[((d * SCHEDROWS + row2) << 6) + L * 2 + (r & 1)] =
                    (unsigned short)ent;
        }
    }
}

// ---------------------------------------------------------------------------
// float2 (complex) radix-8 pieces. phi(m) = m ^ (((m>>4)&7) | (((m>>6)&1)<<3))
// is conflict-free for all FFT load/store patterns used.
// ---------------------------------------------------------------------------
__device__ __forceinline__ int phi(int m) {
    return m ^ (((m >> 4) & 7) | (((m >> 6) & 1) << 3));
}

__device__ __forceinline__ void r8_butterfly(const float* ar, const float* ai,
                                             float* Xr, float* Xi)
{
    float b0r=ar[0]+ar[4], b0i=ai[0]+ai[4];
    float b4r=ar[0]-ar[4], b4i=ai[0]-ai[4];
    float b1r=ar[1]+ar[5], b1i=ai[1]+ai[5];
    float b5r=ar[1]-ar[5], b5i=ai[1]-ai[5];
    float b2r=ar[2]+ar[6], b2i=ai[2]+ai[6];
    float b6r=ar[2]-ar[6], b6i=ai[2]-ai[6];
    float b3r=ar[3]+ar[7], b3i=ai[3]+ai[7];
    float b7r=ar[3]-ar[7], b7i=ai[3]-ai[7];
    float c0r=b0r+b2r, c0i=b0i+b2i;
    float c2r=b0r-b2r, c2i=b0i-b2i;
    float c1r=b1r+b3r, c1i=b1i+b3i;
    float c3r=b1r-b3r, c3i=b1i-b3i;
    float c4r=b4r+b6i, c4i=b4i-b6r;
    float c6r=b4r-b6i, c6i=b4i+b6r;
    float c5r=b5r+b7i, c5i=b5i-b7r;
    float c7r=b5r-b7i, c7i=b5i+b7r;
    Xr[0]=c0r+c1r; Xi[0]=c0i+c1i;
    Xr[4]=c0r-c1r; Xi[4]=c0i-c1i;
    Xr[2]=c2r+c3i; Xi[2]=c2i-c3r;
    Xr[6]=c2r-c3i; Xi[6]=c2i+c3r;
    const float R2 = 0.70710678118654752440f;
    const float u5r=(c5r+c5i)*R2, u5i=(c5i-c5r)*R2;
    Xr[1]=c4r+u5r; Xi[1]=c4i+u5i;
    Xr[5]=c4r-u5r; Xi[5]=c4i-u5i;
    const float u7r=(c7i-c7r)*R2, u7i=-(c7r+c7i)*R2;
    Xr[3]=c6r+u7r; Xi[3]=c6i+u7i;
    Xr[7]=c6r-u7r; Xi[7]=c6i-u7i;
}

template<int S, int MI, int MO>
__device__ __forceinline__ void r8c_stage(const float2* __restrict__ x,
                                          float2* __restrict__ y,
                                          int t, const float2* __restrict__ Wc)
{
    const int p = t / S;
    const int q = t - p * S;
    float ar[8], ai[8];
    #pragma unroll
    for (int j = 0; j < 8; j++) {
        int m = t + 64 * j;
        if (MI) m = phi(m);
        const float2 v = x[m];
        ar[j] = v.x; ai[j] = v.y;
    }
    float Xr[8], Xi[8];
    r8_butterfly(ar, ai, Xr, Xi);

    if (S < 64) {
        const float2 w1 = Wc[S * p];
        float wr = w1.x, wi = w1.y;
        #pragma unroll
        for (int k = 1; k < 8; k++) {
            const float tr = Xr[k]*wr - Xi[k]*wi;
            const float ti = Xr[k]*wi + Xi[k]*wr;
            Xr[k] = tr; Xi[k] = ti;
            const float nr = wr*w1.x - wi*w1.y;
            const float ni = wr*w1.y + wi*w1.x;
            wr = nr; wi = ni;
        }
    }
    #pragma unroll
    for (int k = 0; k < 8; k++) {
        int m = 8*S*p + q + S*k;
        if (MO) m = phi(m);
        y[m] = make_float2(Xr[k], Xi[k]);
    }
}

// Last inverse stage (S=64): registers -> global, coalesced (rows 2s, 2s+1).
__device__ __forceinline__ void r8c_last_inv(const float2* __restrict__ x,
                                             float* __restrict__ o_even,
                                             int t)
{
    float ar[8], ai[8];
    #pragma unroll
    for (int j = 0; j < 8; j++) {
        const float2 v = x[phi(t + 64 * j)];
        ar[j] = v.x; ai[j] = v.y;
    }
    float Xr[8], Xi[8];
    r8_butterfly(ar, ai, Xr, Xi);
    const float inv = 1.0f / 512.0f;
    float* o_odd = o_even + NB;
    #pragma unroll
    for (int k = 0; k < 8; k++) {
        o_even[t + 64 * k] =  Xr[k] * inv;
        o_odd [t + 64 * k] = -Xi[k] * inv;
    }
}

// ---------------------------------------------------------------------------
// Persistent main kernel with bank-scheduled gather (unchanged from R15).
// ---------------------------------------------------------------------------
#define OFF_SCHED  0          // 36864 (u32[3*96*32])
#define OFF_ASSIGN 36864      // 3072  (u16[3*512])
#define OFF_META   39936      // 192: glen2[48] u16, gbase2[48] u16
#define OFF_X      40128      // 32896 (4112 float2: 4096 data + 16 zero pads)
#define OFF_BUF0   73024      // 32768 (float2[8][512])
#define OFF_W      105792     // 512 (float2[64])
#define SMEM_BYTES 106304

__global__ void __launch_bounds__(NTHREADS, 2)
poly_sketch_kernel(const float* __restrict__ X, float* __restrict__ out)
{
    extern __shared__ char sm[];
    unsigned*       shSched  = (unsigned*)(sm + OFF_SCHED);
    unsigned short* shAssign = (unsigned short*)(sm + OFF_ASSIGN);
    unsigned short* shGlen2  = (unsigned short*)(sm + OFF_META);
    unsigned short* shGbase2 = shGlen2 + 48;
    float2* shX2  = (float2*)(sm + OFF_X);
    float2* cbuf1 = (float2*)(sm + OFF_X);      // aliases shX2[0..4095]
    float2* cbuf0 = (float2*)(sm + OFF_BUF0);
    float2* Wc    = (float2*)(sm + OFF_W);
    __shared__ int sh_g;

    const int tid = threadIdx.x;

    {   // load schedule + assign + meta
        for (int i = tid; i < DEG * SCHEDROWS * 32; i += NTHREADS)
            shSched[i] = g_sched[i];
        const unsigned* ga = (const unsigned*)g_assign;
        unsigned* sa = (unsigned*)shAssign;
        for (int i = tid; i < DEG * NB / 2; i += NTHREADS) sa[i] = ga[i];
        if (tid < 48) { shGlen2[tid] = g_glen2[tid]; shGbase2[tid] = g_gbase2[tid]; }
    }
    if (tid < 64) {
        float ang = -6.283185307179586f * (float)tid * (1.0f / 512.0f);
        float s, c; sincosf(ang, &s, &c);
        Wc[tid] = make_float2(c, s);
    }
    if (tid < 16) shX2[4096 + tid] = make_float2(0.f, 0.f);  // pad bank slots
    __syncthreads();

    const int fftid = tid >> 6;
    const int t64 = tid & 63;
    const int wg = tid >> 5;
    const int lane = tid & 31;
    int prev = -1;

    for (;;) {
        if (tid == 0) sh_g = (int)atomicAdd(&g_ctr, 1u);
        __syncthreads();
        const int g = sh_g;
        const bool have = (g < NGROUPS);
        if (!have && prev < 0) break;

        if (have) {
            const int grow = g * 4;
            #pragma unroll
            for (int pp = 0; pp < 2; pp++) {
                const int r0 = grow + 2 * pp;
                {   // stage X pair, interleaved float2, swizzled
                    const float4* X0 = (const float4*)(X + (size_t)r0 * FDIM);
                    const float4* X1 = (const float4*)(X + (size_t)(r0 + 1) * FDIM);
                    #pragma unroll
                    for (int j = 0; j < (FDIM / 4) / NTHREADS; j++) {
                        const int f4 = j * NTHREADS + tid;
                        const float4 v0 = X0[f4];
                        const float4 v1 = X1[f4];
                        const int sidx = 4 * f4;
                        const int wz = (f4 >> 2) & 3;
                        shX2[sidx + (0 ^ wz)] = make_float2(v0.x, v1.x);
                        shX2[sidx + (1 ^ wz)] = make_float2(v0.y, v1.y);
                        shX2[sidx + (2 ^ wz)] = make_float2(v0.z, v1.z);
                        shX2[sidx + (3 ^ wz)] = make_float2(v0.w, v1.w);
                    }
                }
                __syncthreads();
                // scheduled gather: conflict-managed, uniform per-warp loops
                #pragma unroll
                for (int d = 0; d < DEG; d++) {
                    const int rows2 = shGlen2[d * 16 + wg];
                    const unsigned* sp = shSched +
                        ((d * SCHEDROWS + shGbase2[d * 16 + wg]) << 5) + lane;
                    float a0 = 0.f, a1 = 0.f;
                    for (int q2 = 0; q2 < rows2; q2++) {
                        const unsigned w = *sp; sp += 32;
                        const unsigned e0 = w & 0xffffu, e1 = w >> 16;
                        const float2 x0 = shX2[e0 & 0x1fffu];
                        const unsigned m0 = ((~e0) & 0x8000u) << 16;
                        a0 += __int_as_float(__float_as_int(x0.x) ^ m0);
                        a1 += __int_as_float(__float_as_int(x0.y) ^ m0);
                        const float2 x1 = shX2[e1 & 0x1fffu];
                        const unsigned m1 = ((~e1) & 0x8000u) << 16;
                        a0 += __int_as_float(__float_as_int(x1.x) ^ m1);
                        a1 += __int_as_float(__float_as_int(x1.y) ^ m1);
                    }
                    const int B = shAssign[d * NB + tid];
                    cbuf0[(pp * 3 + d) * 512 + B] = make_float2(a0, a1);
                }
                __syncthreads();
            }
        }

        {   // 8-slot radix-8 FFT wave (fwd slots 0-5, inverse slots 6-7)
            const bool active = (fftid < 6) ? have : (prev >= 0);
            if (active) {
                const float2* b0 = cbuf0 + fftid * 512;
                float2*       b1 = cbuf1 + fftid * 512;
                r8c_stage<1, 0, 1>(b0, b1, t64, Wc);
                asm volatile("bar.sync %0, 64;" :: "r"(fftid + 1) : "memory");
                r8c_stage<8, 1, 1>(b1, (float2*)b0, t64, Wc);
                asm volatile("bar.sync %0, 64;" :: "r"(fftid + 1) : "memory");
                if (fftid < 6) {
                    r8c_stage<64, 1, 0>(b0, b1, t64, Wc);
                } else {
                    float* o_even = out + ((size_t)prev * 4 + 2 * (fftid - 6)) * NB;
                    r8c_last_inv(b0, o_even, t64);
                }
            }
        }
        __syncthreads();

        if (have) {  // Hermitian split + 3-way product -> Q directly (slots 6,7)
            const int pp = tid >> 8;
            const int k0 = tid & 255;
            float2* Qs = cbuf0 + (6 + pp) * 512;
            const int nrep = (k0 == 0) ? 2 : 1;
            for (int rep = 0; rep < nrep; rep++) {
                const int k = rep ? 256 : k0;
                const int kr = (NB - k) & (NB - 1);
                float er = 1.f, ei = 0.f, odr = 1.f, odi = 0.f;
                #pragma unroll
                for (int d = 0; d < DEG; d++) {
                    const int slot = pp * 3 + d;
                    const float2 z = cbuf1[slot * 512 + k];
                    const float2 w = cbuf1[slot * 512 + kr];
                    const float ser = 0.5f * (z.x + w.x), sei = 0.5f * (z.y - w.y);
                    const float sor = 0.5f * (z.y + w.y), soi = 0.5f * (w.x - z.x);
                    float tr = er * ser - ei * sei;  ei = er * sei + ei * ser;  er = tr;
                    tr = odr * sor - odi * soi;      odi = odr * soi + odi * sor; odr = tr;
                }
                Qs[k]  = make_float2(er - odi, -(ei + odr));
                Qs[kr] = make_float2(er + odi, ei - odr);
            }
        }
        __syncthreads();
        prev = have ? g : -1;
    }
}

extern "C" void kernel_launch(void* const* d_in, const int* in_sizes, int n_in,
                              void* d_out, int out_size)
{
    const float* X  = (const float*)d_in[0];
    const int*   ih = (const int*)d_in[1];
    const int*   bh = (const int*)d_in[2];
    float* out = (float*)d_out;

    cudaFuncSetAttribute(poly_sketch_kernel,
                         cudaFuncAttributeMaxDynamicSharedMemorySize, SMEM_BYTES);
    build_csr<<<DEG, NTHREADS>>>(ih, bh);
    build_sched<<<DEG, 32>>>();
    poly_sketch_kernel<<<GRID_MAIN, NTHREADS, SMEM_BYTES>>>(X, out);
}

// round 17
// speedup vs baseline: 2.3743x; 2.3743x over previous
#include <cuda_runtime.h>
#include <math.h>

#define NB 512
#define FDIM 4096
#define DEG 3
#define NTHREADS 512
#define BATCH 8192
#define NGROUPS (BATCH / 4)      // 2048 groups of 4 rows
#define GRID_MAIN 296            // 148 SMs x 2 CTAs
#define SCHEDROWS 96             // q2 (u32) rows per degree in the schedule

// Balanced gather tables (built once per launch, deterministic).
// sched entry (u16): PRE-SWIZZLED feature (13 bits; swizzle f^((f>>4)&3);
// 4096+b = zero-pad slot hitting bank b) | sign<<15 (1 -> +x).
__device__ __align__(16) unsigned g_sched[DEG * SCHEDROWS * 32];
__device__ __align__(16) unsigned short g_assign[DEG * NB];  // thread -> bucket
__device__ unsigned short g_glen2[DEG * 16];   // q2-rows per (deg, warp)
__device__ unsigned short g_gbase2[DEG * 16];  // q2-row base per (deg, warp)
__device__ unsigned g_ctr;

// ---------------------------------------------------------------------------
// Prologue: one block per degree. FULLY PARALLEL (no serial scheduling):
// 1) invert hash into per-bucket lists (deterministic chunk-major order)
// 2) sort buckets by (len desc, id asc); warp w owns ranks [32w, 32w+32)
//    -> uniform per-warp row counts (load balance, zero divergence)
// 3) thread t writes its bucket's entries into its own lane column.
// ---------------------------------------------------------------------------
__global__ void __launch_bounds__(NTHREADS)
build_csr(const int* __restrict__ idxh, const int* __restrict__ bith)
{
    __shared__ int hist[8][NB];               // 16 KB
    __shared__ int scanA[NB], scanB[NB];      // 4 KB
    __shared__ int off[NB + 1];               // 2 KB
    __shared__ unsigned short lists[FDIM];    // 8 KB
    __shared__ unsigned short cnt[NB];        // 1 KB
    __shared__ unsigned short sortedIds[NB];  // 1 KB
    __shared__ int rowsArr[16], base2Arr[16];

    const int t = threadIdx.x;
    const int d = blockIdx.x;
    const int w = t >> 5, lane = t & 31;

    if (d == 0 && t == 0) g_ctr = 0;

    for (int i = t; i < 8 * NB; i += NTHREADS) ((int*)hist)[i] = 0;
    __syncthreads();

    if (w < 8) {   // chunk w = features [512w, 512w+512)
        const int base = d * FDIM + w * 512;
        for (int it = 0; it < 16; it++) {
            int b = idxh[base + it * 32 + lane];
            atomicAdd(&hist[w][b], 1);
        }
    }
    __syncthreads();

    {   // totals + inclusive scan -> off
        int c = 0;
        #pragma unroll
        for (int ch = 0; ch < 8; ch++) c += hist[ch][t];
        cnt[t] = (unsigned short)c;
        scanA[t] = c;
    }
    __syncthreads();
    {
        int* s = scanA; int* dd = scanB;
        for (int o = 1; o < NB; o <<= 1) {
            int v = s[t];
            if (t >= o) v += s[t - o];
            dd[t] = v;
            int* tmp = s; s = dd; dd = tmp;
            __syncthreads();
        }
        if (t == 0) off[0] = 0;
        off[t + 1] = s[t];
    }
    __syncthreads();
    {   // per-chunk cursors
        int base = off[t];
        #pragma unroll
        for (int c = 0; c < 8; c++) {
            int h = hist[c][t];
            hist[c][t] = base;
            base += h;
        }
    }
    __syncthreads();

    if (w < 8) {   // stable scatter into lists (pre-swizzled feature index)
        const int fbase = w * 512;
        for (int it = 0; it < 16; it++) {
            int f  = fbase + it * 32 + lane;
            int b  = idxh[d * FDIM + f];
            int sg = bith[d * FDIM + f];
            int fs = f ^ ((f >> 4) & 3);
            unsigned m = __match_any_sync(0xffffffffu, b);
            int rank = __popc(m & ((1u << lane) - 1));
            int grp  = __popc(m);
            int base = hist[w][b];
            lists[base + rank] = (unsigned short)(fs | (sg << 15));
            if (rank == grp - 1) hist[w][b] = base + grp;
            __syncwarp();
        }
    }
    __syncthreads();

    {   // deterministic sort by (len desc, id asc)
        const int myc = cnt[t];
        int gt = 0, eq = 0;
        for (int b2 = 0; b2 < NB; b2++) {
            int c2 = cnt[b2];
            gt += (c2 > myc);
            eq += (c2 == myc && b2 < t);
        }
        sortedIds[gt + eq] = (unsigned short)t;
    }
    __syncthreads();

    g_assign[d * NB + t] = sortedIds[t];

    // rows per warp = len of its longest bucket (rank 32w after sort), even-pad
    if (lane == 0) rowsArr[w] = ((int)cnt[sortedIds[32 * w]] + 1) & ~1;
    __syncthreads();
    if (t == 0) {
        int run = 0;
        for (int g = 0; g < 16; g++) { base2Arr[g] = run; run += rowsArr[g] >> 1; }
    }
    __syncthreads();
    if (lane == 0) {
        int gl = rowsArr[w] >> 1;
        const int b2 = base2Arr[w];
        if (b2 + gl > SCHEDROWS) gl = SCHEDROWS - b2;
        if (gl < 0) gl = 0;
        g_glen2[d * 16 + w]  = (unsigned short)gl;
        g_gbase2[d * 16 + w] = (unsigned short)b2;
    }
    __syncthreads();

    {   // PARALLEL schedule write: thread t owns bucket sortedIds[t]; its
        // entries go down its own lane column. Pads hit zero slot, bank=lane.
        const int B = sortedIds[t];
        const int o = off[B];
        const int n = cnt[B];
        const int rows   = rowsArr[w];           // uniform within warp
        const int base2v = base2Arr[w];
        unsigned short* sched16 = (unsigned short*)g_sched;
        const unsigned short pad = (unsigned short)(0x1000 + (lane & 15));
        for (int i = 0; i < rows; i++) {
            const unsigned short e = (i < n) ? lists[o + i] : pad;
            const int row2 = base2v + (i >> 1);
            if (row2 < SCHEDROWS)
                sched16[((d * SCHEDROWS + row2) << 6) + lane * 2 + (i & 1)] = e;
        }
    }
}

// ---------------------------------------------------------------------------
// float2 (complex) radix-8 pieces. phi(m) = m ^ (((m>>4)&7) | (((m>>6)&1)<<3))
// is conflict-free for all FFT load/store patterns used.
// ---------------------------------------------------------------------------
__device__ __forceinline__ int phi(int m) {
    return m ^ (((m >> 4) & 7) | (((m >> 6) & 1) << 3));
}

__device__ __forceinline__ void r8_butterfly(const float* ar, const float* ai,
                                             float* Xr, float* Xi)
{
    float b0r=ar[0]+ar[4], b0i=ai[0]+ai[4];
    float b4r=ar[0]-ar[4], b4i=ai[0]-ai[4];
    float b1r=ar[1]+ar[5], b1i=ai[1]+ai[5];
    float b5r=ar[1]-ar[5], b5i=ai[1]-ai[5];
    float b2r=ar[2]+ar[6], b2i=ai[2]+ai[6];
    float b6r=ar[2]-ar[6], b6i=ai[2]-ai[6];
    float b3r=ar[3]+ar[7], b3i=ai[3]+ai[7];
    float b7r=ar[3]-ar[7], b7i=ai[3]-ai[7];
    float c0r=b0r+b2r, c0i=b0i+b2i;
    float c2r=b0r-b2r, c2i=b0i-b2i;
    float c1r=b1r+b3r, c1i=b1i+b3i;
    float c3r=b1r-b3r, c3i=b1i-b3i;
    float c4r=b4r+b6i, c4i=b4i-b6r;
    float c6r=b4r-b6i, c6i=b4i+b6r;
    float c5r=b5r+b7i, c5i=b5i-b7r;
    float c7r=b5r-b7i, c7i=b5i+b7r;
    Xr[0]=c0r+c1r; Xi[0]=c0i+c1i;
    Xr[4]=c0r-c1r; Xi[4]=c0i-c1i;
    Xr[2]=c2r+c3i; Xi[2]=c2i-c3r;
    Xr[6]=c2r-c3i; Xi[6]=c2i+c3r;
    const float R2 = 0.70710678118654752440f;
    const float u5r=(c5r+c5i)*R2, u5i=(c5i-c5r)*R2;
    Xr[1]=c4r+u5r; Xi[1]=c4i+u5i;
    Xr[5]=c4r-u5r; Xi[5]=c4i-u5i;
    const float u7r=(c7i-c7r)*R2, u7i=-(c7r+c7i)*R2;
    Xr[3]=c6r+u7r; Xi[3]=c6i+u7i;
    Xr[7]=c6r-u7r; Xi[7]=c6i-u7i;
}

template<int S, int MI, int MO>
__device__ __forceinline__ void r8c_stage(const float2* __restrict__ x,
                                          float2* __restrict__ y,
                                          int t, const float2* __restrict__ Wc)
{
    const int p = t / S;
    const int q = t - p * S;
    float ar[8], ai[8];
    #pragma unroll
    for (int j = 0; j < 8; j++) {
        int m = t + 64 * j;
        if (MI) m = phi(m);
        const float2 v = x[m];
        ar[j] = v.x; ai[j] = v.y;
    }
    float Xr[8], Xi[8];
    r8_butterfly(ar, ai, Xr, Xi);

    if (S < 64) {
        const float2 w1 = Wc[S * p];
        float wr = w1.x, wi = w1.y;
        #pragma unroll
        for (int k = 1; k < 8; k++) {
            const float tr = Xr[k]*wr - Xi[k]*wi;
            const float ti = Xr[k]*wi + Xi[k]*wr;
            Xr[k] = tr; Xi[k] = ti;
            const float nr = wr*w1.x - wi*w1.y;
            const float ni = wr*w1.y + wi*w1.x;
            wr = nr; wi = ni;
        }
    }
    #pragma unroll
    for (int k = 0; k < 8; k++) {
        int m = 8*S*p + q + S*k;
        if (MO) m = phi(m);
        y[m] = make_float2(Xr[k], Xi[k]);
    }
}

// Last inverse stage (S=64): registers -> global, coalesced (rows 2s, 2s+1).
__device__ __forceinline__ void r8c_last_inv(const float2* __restrict__ x,
                                             float* __restrict__ o_even,
                                             int t)
{
    float ar[8], ai[8];
    #pragma unroll
    for (int j = 0; j < 8; j++) {
        const float2 v = x[phi(t + 64 * j)];
        ar[j] = v.x; ai[j] = v.y;
    }
    float Xr[8], Xi[8];
    r8_butterfly(ar, ai, Xr, Xi);
    const float inv = 1.0f / 512.0f;
    float* o_odd = o_even + NB;
    #pragma unroll
    for (int k = 0; k < 8; k++) {
        o_even[t + 64 * k] =  Xr[k] * inv;
        o_odd [t + 64 * k] = -Xi[k] * inv;
    }
}

// ---------------------------------------------------------------------------
// Persistent main kernel with balanced gather (unchanged from R15).
// ---------------------------------------------------------------------------
#define OFF_SCHED  0          // 36864 (u32[3*96*32])
#define OFF_ASSIGN 36864      // 3072  (u16[3*512])
#define OFF_META   39936      // 192: glen2[48] u16, gbase2[48] u16
#define OFF_X      40128      // 32896 (4112 float2: 4096 data + 16 zero pads)
#define OFF_BUF0   73024      // 32768 (float2[8][512])
#define OFF_W      105792     // 512 (float2[64])
#define SMEM_BYTES 106304

__global__ void __launch_bounds__(NTHREADS, 2)
poly_sketch_kernel(const float* __restrict__ X, float* __restrict__ out)
{
    extern __shared__ char sm[];
    unsigned*       shSched  = (unsigned*)(sm + OFF_SCHED);
    unsigned short* shAssign = (unsigned short*)(sm + OFF_ASSIGN);
    unsigned short* shGlen2  = (unsigned short*)(sm + OFF_META);
    unsigned short* shGbase2 = shGlen2 + 48;
    float2* shX2  = (float2*)(sm + OFF_X);
    float2* cbuf1 = (float2*)(sm + OFF_X);      // aliases shX2[0..4095]
    float2* cbuf0 = (float2*)(sm + OFF_BUF0);
    float2* Wc    = (float2*)(sm + OFF_W);
    __shared__ int sh_g;

    const int tid = threadIdx.x;

    {   // load schedule + assign + meta
        for (int i = tid; i < DEG * SCHEDROWS * 32; i += NTHREADS)
            shSched[i] = g_sched[i];
        const unsigned* ga = (const unsigned*)g_assign;
        unsigned* sa = (unsigned*)shAssign;
        for (int i = tid; i < DEG * NB / 2; i += NTHREADS) sa[i] = ga[i];
        if (tid < 48) { shGlen2[tid] = g_glen2[tid]; shGbase2[tid] = g_gbase2[tid]; }
    }
    if (tid < 64) {
        float ang = -6.283185307179586f * (float)tid * (1.0f / 512.0f);
        float s, c; sincosf(ang, &s, &c);
        Wc[tid] = make_float2(c, s);
    }
    if (tid < 16) shX2[4096 + tid] = make_float2(0.f, 0.f);  // pad bank slots
    __syncthreads();

    const int fftid = tid >> 6;
    const int t64 = tid & 63;
    const int wg = tid >> 5;
    const int lane = tid & 31;
    int prev = -1;

    for (;;) {
        if (tid == 0) sh_g = (int)atomicAdd(&g_ctr, 1u);
        __syncthreads();
        const int g = sh_g;
        const bool have = (g < NGROUPS);
        if (!have && prev < 0) break;

        if (have) {
            const int grow = g * 4;
            #pragma unroll
            for (int pp = 0; pp < 2; pp++) {
                const int r0 = grow + 2 * pp;
                {   // stage X pair, interleaved float2, swizzled
                    const float4* X0 = (const float4*)(X + (size_t)r0 * FDIM);
                    const float4* X1 = (const float4*)(X + (size_t)(r0 + 1) * FDIM);
                    #pragma unroll
                    for (int j = 0; j < (FDIM / 4) / NTHREADS; j++) {
                        const int f4 = j * NTHREADS + tid;
                        const float4 v0 = X0[f4];
                        const float4 v1 = X1[f4];
                        const int sidx = 4 * f4;
                        const int wz = (f4 >> 2) & 3;
                        shX2[sidx + (0 ^ wz)] = make_float2(v0.x, v1.x);
                        shX2[sidx + (1 ^ wz)] = make_float2(v0.y, v1.y);
                        shX2[sidx + (2 ^ wz)] = make_float2(v0.z, v1.z);
                        shX2[sidx + (3 ^ wz)] = make_float2(v0.w, v1.w);
                    }
                }
                __syncthreads();
                // balanced gather: uniform per-warp loops
                #pragma unroll
                for (int d = 0; d < DEG; d++) {
                    const int rows2 = shGlen2[d * 16 + wg];
                    const unsigned* sp = shSched +
                        ((d * SCHEDROWS + shGbase2[d * 16 + wg]) << 5) + lane;
                    float a0 = 0.f, a1 = 0.f;
                    for (int q2 = 0; q2 < rows2; q2++) {
                        const unsigned w = *sp; sp += 32;
                        const unsigned e0 = w & 0xffffu, e1 = w >> 16;
                        const float2 x0 = shX2[e0 & 0x1fffu];
                        const unsigned m0 = ((~e0) & 0x8000u) << 16;
                        a0 += __int_as_float(__float_as_int(x0.x) ^ m0);
                        a1 += __int_as_float(__float_as_int(x0.y) ^ m0);
                        const float2 x1 = shX2[e1 & 0x1fffu];
                        const unsigned m1 = ((~e1) & 0x8000u) << 16;
                        a0 += __int_as_float(__float_as_int(x1.x) ^ m1);
                        a1 += __int_as_float(__float_as_int(x1.y) ^ m1);
                    }
                    const int B = shAssign[d * NB + tid];
                    cbuf0[(pp * 3 + d) * 512 + B] = make_float2(a0, a1);
                }
                __syncthreads();
            }
        }

        {   // 8-slot radix-8 FFT wave (fwd slots 0-5, inverse slots 6-7)
            const bool active = (fftid < 6) ? have : (prev >= 0);
            if (active) {
                const float2* b0 = cbuf0 + fftid * 512;
                float2*       b1 = cbuf1 + fftid * 512;
                r8c_stage<1, 0, 1>(b0, b1, t64, Wc);
                asm volatile("bar.sync %0, 64;" :: "r"(fftid + 1) : "memory");
                r8c_stage<8, 1, 1>(b1, (float2*)b0, t64, Wc);
                asm volatile("bar.sync %0, 64;" :: "r"(fftid + 1) : "memory");
                if (fftid < 6) {
                    r8c_stage<64, 1, 0>(b0, b1, t64, Wc);
                } else {
                    float* o_even = out + ((size_t)prev * 4 + 2 * (fftid - 6)) * NB;
                    r8c_last_inv(b0, o_even, t64);
                }
            }
        }
        __syncthreads();

        if (have) {  // Hermitian split + 3-way product -> Q directly (slots 6,7)
            const int pp = tid >> 8;
            const int k0 = tid & 255;
            float2* Qs = cbuf0 + (6 + pp) * 512;
            const int nrep = (k0 == 0) ? 2 : 1;
            for (int rep = 0; rep < nrep; rep++) {
                const int k = rep ? 256 : k0;
                const int kr = (NB - k) & (NB - 1);
                float er = 1.f, ei = 0.f, odr = 1.f, odi = 0.f;
                #pragma unroll
                for (int d = 0; d < DEG; d++) {
                    const int slot = pp * 3 + d;
                    const float2 z = cbuf1[slot * 512 + k];
                    const float2 w = cbuf1[slot * 512 + kr];
                    const float ser = 0.5f * (z.x + w.x), sei = 0.5f * (z.y - w.y);
                    const float sor = 0.5f * (z.y + w.y), soi = 0.5f * (w.x - z.x);
                    float tr = er * ser - ei * sei;  ei = er * sei + ei * ser;  er = tr;
                    tr = odr * sor - odi * soi;      odi = odr * soi + odi * sor; odr = tr;
                }
                Qs[k]  = make_float2(er - odi, -(ei + odr));
                Qs[kr] = make_float2(er + odi, ei - odr);
            }
        }
        __syncthreads();
        prev = have ? g : -1;
    }
}

extern "C" void kernel_launch(void* const* d_in, const int* in_sizes, int n_in,
                              void* d_out, int out_size)
{
    const float* X  = (const float*)d_in[0];
    const int*   ih = (const int*)d_in[1];
    const int*   bh = (const int*)d_in[2];
    float* out = (float*)d_out;

    cudaFuncSetAttribute(poly_sketch_kernel,
                         cudaFuncAttributeMaxDynamicSharedMemorySize, SMEM_BYTES);
    build_csr<<<DEG, NTHREADS>>>(ih, bh);
    poly_sketch_kernel<<<GRID_MAIN, NTHREADS, SMEM_BYTES>>>(X, out);
}